// round 15
// baseline (speedup 1.0000x reference)
#include <cuda_runtime.h>
#include <cuda.h>
#include <cuda_fp16.h>
#include <cstdint>

#define M_DIM 8192
#define K_DIM 4096
#define N_DIM 11008

// ---------------- scratch (device globals; no runtime allocation) ----------
__device__ __half g_Ah[(size_t)M_DIM * K_DIM];   // A in fp16, [M, K] row-major
__device__ __half g_Wt[(size_t)N_DIM * K_DIM];   // W^T dequant fp16, [N, K] row-major

// ---------------- fused pre-pass: A fp32->fp16  +  int4 dequant->Wt[N,K] ---
static constexpr int A_BLOCKS = (int)(((size_t)M_DIM * K_DIM / 4) / 1024);  // 8192 (4 float4/thr)
static constexpr int W_BLOCKS = (K_DIM / 64) * (N_DIM / 32);                 // 22016

__global__ void prep_kernel(const float* __restrict__ a, const int* __restrict__ w,
                            const float* __restrict__ scale, const int* __restrict__ zp) {
    __shared__ int sw[32][33];
    __shared__ float ssc[32];
    __shared__ float szp[32];
    int t = threadIdx.x;
    if (blockIdx.x < A_BLOCKS) {
        size_t base = (size_t)blockIdx.x * 1024 + t;
#pragma unroll
        for (int j = 0; j < 4; j++) {
            size_t i = base + j * 256;
            float4 v = reinterpret_cast<const float4*>(a)[i];
            __half2 h0 = __floats2half2_rn(v.x, v.y);
            __half2 h1 = __floats2half2_rn(v.z, v.w);
            uint2 o;
            o.x = *reinterpret_cast<uint32_t*>(&h0);
            o.y = *reinterpret_cast<uint32_t*>(&h1);
            reinterpret_cast<uint2*>(g_Ah)[i] = o;
        }
        return;
    }
    int b = blockIdx.x - A_BLOCKS;
    int kt = b & 63;                   // 64 k per tile; group = kt>>1 (gs=128)
    int nt = b >> 6;
    int kp0 = kt * 32, n0 = nt * 32;
    int g = kt >> 1;
    for (int i = t; i < 1024; i += 256) {
        int r = i >> 5, c = i & 31;
        sw[r][c] = w[(size_t)(kp0 + r) * N_DIM + (n0 + c)];
    }
    if (t < 32) {
        ssc[t] = scale[(size_t)g * N_DIM + n0 + t];
        szp[t] = (float)zp[(size_t)g * N_DIM + n0 + t];
    }
    __syncthreads();
    int nl = t >> 3;
    int kq = (t & 7) * 4;
    float sc = ssc[nl], z = szp[nl];
    __half2 outv[4];
#pragma unroll
    for (int j = 0; j < 4; j++) {
        int wv = sw[kq + j][nl];
        outv[j] = __floats2half2_rn(((float)(wv & 0xF) - z) * sc,
                                    ((float)((wv >> 4) & 0xF) - z) * sc);
    }
    size_t off = (size_t)(n0 + nl) * K_DIM + (size_t)kt * 64 + kq * 2;
    *reinterpret_cast<float4*>(&g_Wt[off]) = *reinterpret_cast<float4*>(outv);
}

// ---------------- main GEMM: mma.sync m16n8k16 + TMA ----------------------
// 2 CTAs/SM x 8 warps (warp tile 32x64); 3 stages; single-thread TMA producer.
// Fully decoupled waits: consumer full-wait = probe@step4 + reprobe@step12 +
// rare blocking spin; producer empty-wait = probe at top (fill now) else
// deferred fill after the step loop (laggards get a full iteration).
static constexpr int BM = 128, BN = 128, BK = 64, STAGES = 3;
static constexpr int A_ST = BM * BK * 2;                 // 16384 (A part of stage)
static constexpr int STAGE_BYTES = 2 * A_ST;             // 32768 (A then B)
static constexpr int MBAR_OFF = STAGES * STAGE_BYTES;    // 98304
static constexpr int GEMM_SMEM = MBAR_OFF + 64;          // 98368 (x2 CTA = 196736)
static constexpr int TM_TILES = M_DIM / BM;   // 64
static constexpr int TN_TILES = N_DIM / BN;   // 86
static constexpr int KITERS = K_DIM / BK;     // 64

__device__ __forceinline__ uint32_t smem_u32(const void* p) {
    uint32_t a;
    asm("{ .reg .u64 t; cvta.to.shared.u64 t, %1; cvt.u32.u64 %0, t; }" : "=r"(a) : "l"(p));
    return a;
}

#define TMA_LOAD_2D(smem_addr, tmap, cx, cy, mbar) \
    asm volatile("cp.async.bulk.tensor.2d.shared::cta.global.tile.mbarrier::complete_tx::bytes " \
                 "[%0], [%1, {%2, %3}], [%4];" \
                 :: "r"((uint32_t)(smem_addr)), "l"(tmap), "r"((int32_t)(cx)), "r"((int32_t)(cy)), \
                    "r"((uint32_t)(mbar)) : "memory")

#define MBARRIER_INIT(addr, cnt) \
    asm volatile("mbarrier.init.shared.b64 [%0], %1;" :: "r"((uint32_t)(addr)), "r"((uint32_t)(cnt)) : "memory")

#define MBARRIER_EXPECT_TX(addr, bytes) \
    asm volatile("mbarrier.arrive.expect_tx.shared.b64 _, [%0], %1;" :: "r"((uint32_t)(addr)), "r"((uint32_t)(bytes)) : "memory")

#define MBARRIER_ARRIVE(addr) \
    asm volatile("mbarrier.arrive.shared.b64 _, [%0];" :: "r"((uint32_t)(addr)) : "memory")

#define FENCE_PROXY_ASYNC() \
    asm volatile("fence.proxy.async.shared::cta;" ::: "memory")

// non-blocking acquire probe (consumer)
#define MBARRIER_TRY_PROBE(addr, parity, outreg) \
    asm volatile("{\n\t.reg .pred p;\n\t" \
        "mbarrier.try_wait.parity.acquire.cta.shared::cta.b64 p, [%1], %2;\n\t" \
        "selp.b32 %0, 1, 0, p;\n\t}" : "=r"(outreg) : "r"((uint32_t)(addr)), "r"((uint32_t)(parity)) : "memory")

// non-blocking relaxed probe (producer; post-success smem writes are TMA/async)
#define MBARRIER_TRY_PROBE_RELAXED(addr, parity, outreg) \
    asm volatile("{\n\t.reg .pred p;\n\t" \
        "mbarrier.try_wait.parity.relaxed.cta.shared::cta.b64 p, [%1], %2;\n\t" \
        "selp.b32 %0, 1, 0, p;\n\t}" : "=r"(outreg) : "r"((uint32_t)(addr)), "r"((uint32_t)(parity)) : "memory")

// blocking acquire wait (spin)
#define MBARRIER_WAIT_PARITY(addr, parity) do { \
    uint32_t _m = (uint32_t)(addr); \
    uint32_t _p = (uint32_t)(parity); \
    asm volatile("{\n\t.reg .pred P1;\n\t" \
        "WL_%=:\n\t" \
        "mbarrier.try_wait.parity.acquire.cta.shared::cta.b64 P1, [%0], %1, 0x989680;\n\t" \
        "@P1 bra.uni WD_%=;\n\t" \
        "bra.uni WL_%=;\n\t" \
        "WD_%=:\n\t}" :: "r"(_m), "r"(_p) : "memory"); \
} while (0)

// blocking relaxed wait (producer slow path)
#define MBARRIER_WAIT_PARITY_RELAXED(addr, parity) do { \
    uint32_t _m = (uint32_t)(addr); \
    uint32_t _p = (uint32_t)(parity); \
    asm volatile("{\n\t.reg .pred P1;\n\t" \
        "WL_%=:\n\t" \
        "mbarrier.try_wait.parity.relaxed.cta.shared::cta.b64 P1, [%0], %1, 0x989680;\n\t" \
        "@P1 bra.uni WD_%=;\n\t" \
        "bra.uni WL_%=;\n\t" \
        "WD_%=:\n\t}" :: "r"(_m), "r"(_p) : "memory"); \
} while (0)

#define LDSM_X4(r0, r1, r2, r3, addr) \
    asm volatile("ldmatrix.sync.aligned.m8n8.x4.shared.b16 {%0,%1,%2,%3}, [%4];" \
                 : "=r"(r0), "=r"(r1), "=r"(r2), "=r"(r3) : "r"(addr))

#define MMA_16816(c, a0, a1, a2, a3, b0, b1) \
    asm volatile("mma.sync.aligned.m16n8k16.row.col.f32.f16.f16.f32 " \
                 "{%0,%1,%2,%3}, {%4,%5,%6,%7}, {%8,%9}, {%0,%1,%2,%3};" \
                 : "+f"((c)[0]), "+f"((c)[1]), "+f"((c)[2]), "+f"((c)[3]) \
                 : "r"(a0), "r"(a1), "r"(a2), "r"(a3), "r"(b0), "r"(b1))

__global__ void __launch_bounds__(256, 2) gemm_kernel(
    const __grid_constant__ CUtensorMap tmA,
    const __grid_constant__ CUtensorMap tmB,
    float* __restrict__ out)
{
    extern __shared__ __align__(1024) char smem[];
    uint32_t sb = smem_u32(smem);
    int tid = threadIdx.x, wid = tid >> 5, lane = tid & 31;

    // mbarriers: full[s] @ MBAR_OFF + 8s ; empty[s] @ MBAR_OFF + 24 + 8s
    uint32_t mbFull = sb + MBAR_OFF;
    uint32_t mbEmpty = sb + MBAR_OFF + 24;
    if (tid == 0) {
#pragma unroll
        for (int s = 0; s < STAGES; s++) {
            MBARRIER_INIT(mbFull + 8 * s, 1);      // single expect_tx arrive + tx bytes
            MBARRIER_INIT(mbEmpty + 8 * s, 8);     // one arrival per warp
        }
        FENCE_PROXY_ASYNC();                       // order init before TMA completes
    }
    __syncthreads();   // only barrier in the kernel

    // GROUP_M=16 tile ordering for L2 reuse (64 M-tiles = 4 exact groups)
    constexpr int GROUP_M = 16;
    int pid = blockIdx.x;
    int group_size = GROUP_M * TN_TILES;
    int group_id = pid / group_size;
    int pid_m = group_id * GROUP_M + (pid % GROUP_M);
    int pid_n = (pid % group_size) / GROUP_M;
    int m0 = pid_m * BM, n0 = pid_n * BN;

    // warp grid 4 (m) x 2 (n); warp tile 32 x 64
    int wm = wid & 3, wn = wid >> 2;
    int m0w = wm * 32, n0w = wn * 64;

    // --- per-lane LINEAR LDSM bases + SW128 XOR masks -----------------------
    // addr = (linear base + rowStep + kChunk*32) ^ ((row&7)<<4)
    int lrow = lane & 15;
    int lcol8 = lane >> 4;         // 0/1 -> k offset 0/8 halfs (16B)
    uint32_t aXm = (uint32_t)((m0w + lrow) & 7) << 4;   // row&7 invariant under +16 rows
    uint32_t bXm = (uint32_t)((n0w + lrow) & 7) << 4;
    uint32_t aLinBase = sb + (uint32_t)(m0w + lrow) * 128 + lcol8 * 16;
    uint32_t bLinBase = sb + A_ST + (uint32_t)(n0w + lrow) * 128 + lcol8 * 16;

    float acc[2][8][4];
#pragma unroll
    for (int mt = 0; mt < 2; mt++)
#pragma unroll
        for (int nt = 0; nt < 8; nt++)
#pragma unroll
            for (int j = 0; j < 4; j++) acc[mt][nt][j] = 0.f;

    // --- prologue: producer (tid 0) fills stages 0,1 ---
    if (tid == 0) {
#pragma unroll
        for (int s = 0; s < STAGES - 1; s++) {
            uint32_t so = sb + s * STAGE_BYTES;
            MBARRIER_EXPECT_TX(mbFull + 8 * s, STAGE_BYTES);
            TMA_LOAD_2D(so, &tmA, s * BK, m0, mbFull + 8 * s);
            TMA_LOAD_2D(so + A_ST, &tmB, s * BK, n0, mbFull + 8 * s);
        }
    }

    // pipeline state: sc = consume stage, pc = its full parity;
    // sf = fill stage for iter kt+2; pe = producer's empty parity.
    int sc = 0, pc = 0;
    int sf = 2, pe = 0;
    uint32_t rdy = 0;    // consumer probe result (0 at kt=0 -> spin)

    for (int kt = 0; kt < KITERS; kt++) {
        if (!rdy) MBARRIER_WAIT_PARITY(mbFull + 8 * sc, pc);   // slow path only

        uint32_t so = sc * STAGE_BYTES;
        uint32_t aB = aLinBase + so, bB = bLinBase + so;

        // next-stage probe target
        int scn = (sc == STAGES - 1) ? 0 : sc + 1;
        int pcn = (sc == STAGES - 1) ? (pc ^ 1) : pc;

        // preload first fragments of this stage
        uint32_t af[2][2][4];        // [k16 buf][mt][frag]
        uint32_t bf[3][4];           // [step mod 3][frag] — distance-2 prefetch
        LDSM_X4(af[0][0][0], af[0][0][1], af[0][0][2], af[0][0][3], aB ^ aXm);
        LDSM_X4(af[0][1][0], af[0][1][1], af[0][1][2], af[0][1][3], (aB + 2048) ^ aXm);
        LDSM_X4(bf[0][0], bf[0][1], bf[0][2], bf[0][3], bB ^ bXm);                    // step 0
        LDSM_X4(bf[1][0], bf[1][1], bf[1][2], bf[1][3], (bB + 2048) ^ bXm);           // step 1

        // producer fast path: probe empty[sf]; fill now if already released
        uint32_t filled = 1;   // covers "no fill needed" and kt==0 (first fill of s2)
        if (tid == 0 && kt + 2 < KITERS) {
            uint32_t eRdy = 1;
            if (kt > 0) MBARRIER_TRY_PROBE_RELAXED(mbEmpty + 8 * sf, pe, eRdy);
            if (eRdy) {
                uint32_t soN = sb + sf * STAGE_BYTES;
                MBARRIER_EXPECT_TX(mbFull + 8 * sf, STAGE_BYTES);
                TMA_LOAD_2D(soN, &tmA, (kt + 2) * BK, m0, mbFull + 8 * sf);
                TMA_LOAD_2D(soN + A_ST, &tmB, (kt + 2) * BK, n0, mbFull + 8 * sf);
            } else {
                filled = 0;    // defer to after the step loop
            }
        }

        // 16 software-pipelined (k16, nq) steps; B prefetch distance 2
#pragma unroll
        for (int s = 0; s < 16; s++) {
            const int ks = s >> 2, nq = s & 3;
            const int cb = ks & 1, sbuf = s % 3;
            if (nq == 0 && ks < 3) {     // prefetch next k16's A frags
                const int kn = ks + 1, an = kn & 1;
                LDSM_X4(af[an][0][0], af[an][0][1], af[an][0][2], af[an][0][3],
                        (aB + kn * 32) ^ aXm);
                LDSM_X4(af[an][1][0], af[an][1][1], af[an][1][2], af[an][1][3],
                        (aB + 2048 + kn * 32) ^ aXm);
            }
            if (s < 14) {                // prefetch step s+2's B frags
                const int s2 = s + 2, ks2 = s2 >> 2, nq2 = s2 & 3, bn = s2 % 3;
                LDSM_X4(bf[bn][0], bf[bn][1], bf[bn][2], bf[bn][3],
                        (bB + nq2 * 2048 + ks2 * 32) ^ bXm);
            }
            if (s == 4) {                // early probe; covered by steps 5..15
                if (kt + 1 < KITERS) {
                    MBARRIER_TRY_PROBE(mbFull + 8 * scn, pcn, rdy);
                } else {
                    rdy = 1;
                }
            }
            if (s == 12 && kt + 1 < KITERS && !rdy) {   // re-probe if missed
                MBARRIER_TRY_PROBE(mbFull + 8 * scn, pcn, rdy);
            }
#pragma unroll
            for (int mt = 0; mt < 2; mt++) {
                MMA_16816(acc[mt][2 * nq], af[cb][mt][0], af[cb][mt][1],
                          af[cb][mt][2], af[cb][mt][3], bf[sbuf][0], bf[sbuf][2]);
                MMA_16816(acc[mt][2 * nq + 1], af[cb][mt][0], af[cb][mt][1],
                          af[cb][mt][2], af[cb][mt][3], bf[sbuf][1], bf[sbuf][3]);
            }
        }

        // producer slow path: laggard warps had a full step-loop to release sf
        if (tid == 0 && !filled) {
            MBARRIER_WAIT_PARITY_RELAXED(mbEmpty + 8 * sf, pe);
            uint32_t soN = sb + sf * STAGE_BYTES;
            MBARRIER_EXPECT_TX(mbFull + 8 * sf, STAGE_BYTES);
            TMA_LOAD_2D(soN, &tmA, (kt + 2) * BK, m0, mbFull + 8 * sf);
            TMA_LOAD_2D(soN + A_ST, &tmB, (kt + 2) * BK, n0, mbFull + 8 * sf);
        }

        // warp-collective MMAs consumed all this warp's reads of stage sc;
        // single lane releases for the whole warp (empty count = 8)
        if (lane == 0) MBARRIER_ARRIVE(mbEmpty + 8 * sc);

        // advance stage counters / parities
        if (sc == 0 && kt > 0) pe ^= 1;
        sc = scn; pc = pcn;
        if (++sf == STAGES) { sf = 0; }
    }

    // --- epilogue ---
    int gq = lane >> 2, t4 = lane & 3;
#pragma unroll
    for (int mt = 0; mt < 2; mt++) {
        int mrow0 = m0 + m0w + mt * 16 + gq;
#pragma unroll
        for (int nt = 0; nt < 8; nt++) {
            int ncol = n0 + n0w + nt * 8 + t4 * 2;
            float2 v0 = make_float2(acc[mt][nt][0], acc[mt][nt][1]);
            float2 v1 = make_float2(acc[mt][nt][2], acc[mt][nt][3]);
            *reinterpret_cast<float2*>(&out[(size_t)mrow0 * N_DIM + ncol]) = v0;
            *reinterpret_cast<float2*>(&out[(size_t)(mrow0 + 8) * N_DIM + ncol]) = v1;
        }
    }
}

// ---------------- host launch ----------------------------------------------
typedef CUresult (*PFN_tmapEncode)(CUtensorMap*, CUtensorMapDataType, cuuint32_t, void*,
                                   const cuuint64_t*, const cuuint64_t*, const cuuint32_t*,
                                   const cuuint32_t*, CUtensorMapInterleave, CUtensorMapSwizzle,
                                   CUtensorMapL2promotion, CUtensorMapFloatOOBfill);

extern "C" void kernel_launch(void* const* d_in, const int* in_sizes, int n_in,
                              void* d_out, int out_size) {
    const float* A = (const float*)d_in[0];
    const int*   W = (const int*)d_in[1];
    const float* S = (const float*)d_in[2];
    const int*   Z = (const int*)d_in[3];
    float* out = (float*)d_out;

    void* pAh = nullptr;
    void* pWt = nullptr;
    cudaGetSymbolAddress(&pAh, g_Ah);
    cudaGetSymbolAddress(&pWt, g_Wt);

    PFN_tmapEncode enc = nullptr;
    cudaDriverEntryPointQueryResult qr;
    cudaGetDriverEntryPointByVersion("cuTensorMapEncodeTiled", (void**)&enc, 12000,
                                     cudaEnableDefault, &qr);

    CUtensorMap tmA, tmB;
    {
        cuuint64_t dims[2]    = {K_DIM, M_DIM};
        cuuint64_t strides[1] = {K_DIM * 2};
        cuuint32_t box[2]     = {BK, BM};       // 64 fp16 = 128B row (SW128), 128 rows
        cuuint32_t es[2]      = {1, 1};
        enc(&tmA, CU_TENSOR_MAP_DATA_TYPE_FLOAT16, 2, pAh, dims, strides, box, es,
            CU_TENSOR_MAP_INTERLEAVE_NONE, CU_TENSOR_MAP_SWIZZLE_128B,
            CU_TENSOR_MAP_L2_PROMOTION_L2_128B, CU_TENSOR_MAP_FLOAT_OOB_FILL_NONE);
    }
    {
        cuuint64_t dims[2]    = {K_DIM, N_DIM};
        cuuint64_t strides[1] = {K_DIM * 2};
        cuuint32_t box[2]     = {BK, BN};
        cuuint32_t es[2]      = {1, 1};
        enc(&tmB, CU_TENSOR_MAP_DATA_TYPE_FLOAT16, 2, pWt, dims, strides, box, es,
            CU_TENSOR_MAP_INTERLEAVE_NONE, CU_TENSOR_MAP_SWIZZLE_128B,
            CU_TENSOR_MAP_L2_PROMOTION_L2_128B, CU_TENSOR_MAP_FLOAT_OOB_FILL_NONE);
    }

    cudaFuncSetAttribute(gemm_kernel, cudaFuncAttributeMaxDynamicSharedMemorySize, GEMM_SMEM);

    prep_kernel<<<A_BLOCKS + W_BLOCKS, 256>>>(A, W, S, Z);
    gemm_kernel<<<TM_TILES * TN_TILES, 256, GEMM_SMEM>>>(tmA, tmB, out);
}

// round 16
// speedup vs baseline: 1.0548x; 1.0548x over previous
#include <cuda_runtime.h>
#include <cuda.h>
#include <cuda_fp16.h>
#include <cstdint>

#define M_DIM 8192
#define K_DIM 4096
#define N_DIM 11008

// ---------------- scratch (device globals; no runtime allocation) ----------
__device__ __half g_Ah[(size_t)M_DIM * K_DIM];   // A in fp16, [M, K] row-major
__device__ __half g_Wt[(size_t)N_DIM * K_DIM];   // W^T dequant fp16, [N, K] row-major

// ---------------- fused pre-pass: A fp32->fp16  +  int4 dequant->Wt[N,K] ---
// A: 4 float4 per thread (MLP 4). W: 64k x 64n per block, int4 loads (MLP 8).
static constexpr int A_BLOCKS = (int)(((size_t)M_DIM * K_DIM / 4) / 1024);  // 8192
static constexpr int W_BLOCKS = (K_DIM / 64) * (N_DIM / 64);                 // 11008

__global__ void prep_kernel(const float* __restrict__ a, const int* __restrict__ w,
                            const float* __restrict__ scale, const int* __restrict__ zp) {
    __shared__ int sw[32][65];
    __shared__ float ssc[64];
    __shared__ float szp[64];
    int t = threadIdx.x;
    if (blockIdx.x < A_BLOCKS) {
        size_t base = (size_t)blockIdx.x * 1024 + t;
#pragma unroll
        for (int j = 0; j < 4; j++) {
            size_t i = base + j * 256;
            float4 v = reinterpret_cast<const float4*>(a)[i];
            __half2 h0 = __floats2half2_rn(v.x, v.y);
            __half2 h1 = __floats2half2_rn(v.z, v.w);
            uint2 o;
            o.x = *reinterpret_cast<uint32_t*>(&h0);
            o.y = *reinterpret_cast<uint32_t*>(&h1);
            reinterpret_cast<uint2*>(g_Ah)[i] = o;
        }
        return;
    }
    int b = blockIdx.x - A_BLOCKS;
    int kt = b & 63;                   // 64 k per tile (32 packed rows); group = kt>>1
    int nt = b >> 6;                   // 0..171, 64 n per tile
    int kp0 = kt * 32, n0 = nt * 64;
    int g = kt >> 1;
    // coalesced int4 loads: 32 rows x 16 int4/row = 512 int4; 2 per thread
#pragma unroll
    for (int q = 0; q < 2; q++) {
        int idx = t + q * 256;
        int r = idx >> 4, c4 = idx & 15;
        int4 v = *reinterpret_cast<const int4*>(&w[(size_t)(kp0 + r) * N_DIM + n0 + c4 * 4]);
        sw[r][c4 * 4 + 0] = v.x;
        sw[r][c4 * 4 + 1] = v.y;
        sw[r][c4 * 4 + 2] = v.z;
        sw[r][c4 * 4 + 3] = v.w;
    }
    if (t < 64) {
        ssc[t] = scale[(size_t)g * N_DIM + n0 + t];
        szp[t] = (float)zp[(size_t)g * N_DIM + n0 + t];
    }
    __syncthreads();
    int nl = t >> 2;            // local n 0..63
    int kq = (t & 3) * 8;       // packed-row start (8 packed rows = 16 k)
    float sc = ssc[nl], z = szp[nl];
    __half2 outv[8];
#pragma unroll
    for (int j = 0; j < 8; j++) {
        int wv = sw[kq + j][nl];
        outv[j] = __floats2half2_rn(((float)(wv & 0xF) - z) * sc,
                                    ((float)((wv >> 4) & 0xF) - z) * sc);
    }
    size_t off = (size_t)(n0 + nl) * K_DIM + (size_t)kt * 64 + kq * 2;
    *reinterpret_cast<float4*>(&g_Wt[off]) = *reinterpret_cast<float4*>(&outv[0]);
    *reinterpret_cast<float4*>(&g_Wt[off + 8]) = *reinterpret_cast<float4*>(&outv[4]);
}

// ---------------- main GEMM: mma.sync m16n8k16 + TMA (exact R14 state) -----
// 2 CTAs/SM x 8 warps (warp tile 32x64); 3 stages; single-thread TMA producer.
// Consumer full-wait SPLIT: non-blocking acquire probe at step 8, blocking
// spin only if missed. Producer keeps blocking relaxed wait (lead > slots).
static constexpr int BM = 128, BN = 128, BK = 64, STAGES = 3;
static constexpr int A_ST = BM * BK * 2;                 // 16384 (A part of stage)
static constexpr int STAGE_BYTES = 2 * A_ST;             // 32768 (A then B)
static constexpr int MBAR_OFF = STAGES * STAGE_BYTES;    // 98304
static constexpr int GEMM_SMEM = MBAR_OFF + 64;          // 98368 (x2 CTA = 196736)
static constexpr int TM_TILES = M_DIM / BM;   // 64
static constexpr int TN_TILES = N_DIM / BN;   // 86
static constexpr int KITERS = K_DIM / BK;     // 64

__device__ __forceinline__ uint32_t smem_u32(const void* p) {
    uint32_t a;
    asm("{ .reg .u64 t; cvta.to.shared.u64 t, %1; cvt.u32.u64 %0, t; }" : "=r"(a) : "l"(p));
    return a;
}

#define TMA_LOAD_2D(smem_addr, tmap, cx, cy, mbar) \
    asm volatile("cp.async.bulk.tensor.2d.shared::cta.global.tile.mbarrier::complete_tx::bytes " \
                 "[%0], [%1, {%2, %3}], [%4];" \
                 :: "r"((uint32_t)(smem_addr)), "l"(tmap), "r"((int32_t)(cx)), "r"((int32_t)(cy)), \
                    "r"((uint32_t)(mbar)) : "memory")

#define MBARRIER_INIT(addr, cnt) \
    asm volatile("mbarrier.init.shared.b64 [%0], %1;" :: "r"((uint32_t)(addr)), "r"((uint32_t)(cnt)) : "memory")

#define MBARRIER_EXPECT_TX(addr, bytes) \
    asm volatile("mbarrier.arrive.expect_tx.shared.b64 _, [%0], %1;" :: "r"((uint32_t)(addr)), "r"((uint32_t)(bytes)) : "memory")

#define MBARRIER_ARRIVE(addr) \
    asm volatile("mbarrier.arrive.shared.b64 _, [%0];" :: "r"((uint32_t)(addr)) : "memory")

#define FENCE_PROXY_ASYNC() \
    asm volatile("fence.proxy.async.shared::cta;" ::: "memory")

// non-blocking acquire probe: result consumed much later (latency hiding)
#define MBARRIER_TRY_PROBE(addr, parity, outreg) \
    asm volatile("{\n\t.reg .pred p;\n\t" \
        "mbarrier.try_wait.parity.acquire.cta.shared::cta.b64 p, [%1], %2;\n\t" \
        "selp.b32 %0, 1, 0, p;\n\t}" : "=r"(outreg) : "r"((uint32_t)(addr)), "r"((uint32_t)(parity)) : "memory")

// blocking acquire wait (spin)
#define MBARRIER_WAIT_PARITY(addr, parity) do { \
    uint32_t _m = (uint32_t)(addr); \
    uint32_t _p = (uint32_t)(parity); \
    asm volatile("{\n\t.reg .pred P1;\n\t" \
        "WL_%=:\n\t" \
        "mbarrier.try_wait.parity.acquire.cta.shared::cta.b64 P1, [%0], %1, 0x989680;\n\t" \
        "@P1 bra.uni WD_%=;\n\t" \
        "bra.uni WL_%=;\n\t" \
        "WD_%=:\n\t}" :: "r"(_m), "r"(_p) : "memory"); \
} while (0)

// relaxed wait: producer side only (post-wait smem writes are TMA = async proxy)
#define MBARRIER_WAIT_PARITY_RELAXED(addr, parity) do { \
    uint32_t _m = (uint32_t)(addr); \
    uint32_t _p = (uint32_t)(parity); \
    asm volatile("{\n\t.reg .pred P1;\n\t" \
        "WL_%=:\n\t" \
        "mbarrier.try_wait.parity.relaxed.cta.shared::cta.b64 P1, [%0], %1, 0x989680;\n\t" \
        "@P1 bra.uni WD_%=;\n\t" \
        "bra.uni WL_%=;\n\t" \
        "WD_%=:\n\t}" :: "r"(_m), "r"(_p) : "memory"); \
} while (0)

#define LDSM_X4(r0, r1, r2, r3, addr) \
    asm volatile("ldmatrix.sync.aligned.m8n8.x4.shared.b16 {%0,%1,%2,%3}, [%4];" \
                 : "=r"(r0), "=r"(r1), "=r"(r2), "=r"(r3) : "r"(addr))

#define MMA_16816(c, a0, a1, a2, a3, b0, b1) \
    asm volatile("mma.sync.aligned.m16n8k16.row.col.f32.f16.f16.f32 " \
                 "{%0,%1,%2,%3}, {%4,%5,%6,%7}, {%8,%9}, {%0,%1,%2,%3};" \
                 : "+f"((c)[0]), "+f"((c)[1]), "+f"((c)[2]), "+f"((c)[3]) \
                 : "r"(a0), "r"(a1), "r"(a2), "r"(a3), "r"(b0), "r"(b1))

__global__ void __launch_bounds__(256, 2) gemm_kernel(
    const __grid_constant__ CUtensorMap tmA,
    const __grid_constant__ CUtensorMap tmB,
    float* __restrict__ out)
{
    extern __shared__ __align__(1024) char smem[];
    uint32_t sb = smem_u32(smem);
    int tid = threadIdx.x, wid = tid >> 5, lane = tid & 31;

    // mbarriers: full[s] @ MBAR_OFF + 8s ; empty[s] @ MBAR_OFF + 24 + 8s
    uint32_t mbFull = sb + MBAR_OFF;
    uint32_t mbEmpty = sb + MBAR_OFF + 24;
    if (tid == 0) {
#pragma unroll
        for (int s = 0; s < STAGES; s++) {
            MBARRIER_INIT(mbFull + 8 * s, 1);      // single expect_tx arrive + tx bytes
            MBARRIER_INIT(mbEmpty + 8 * s, 8);     // one arrival per warp
        }
        FENCE_PROXY_ASYNC();                       // order init before TMA completes
    }
    __syncthreads();   // only barrier in the kernel

    // GROUP_M=16 tile ordering for L2 reuse (64 M-tiles = 4 exact groups)
    constexpr int GROUP_M = 16;
    int pid = blockIdx.x;
    int group_size = GROUP_M * TN_TILES;
    int group_id = pid / group_size;
    int pid_m = group_id * GROUP_M + (pid % GROUP_M);
    int pid_n = (pid % group_size) / GROUP_M;
    int m0 = pid_m * BM, n0 = pid_n * BN;

    // warp grid 4 (m) x 2 (n); warp tile 32 x 64
    int wm = wid & 3, wn = wid >> 2;
    int m0w = wm * 32, n0w = wn * 64;

    // --- per-lane LINEAR LDSM bases + SW128 XOR masks -----------------------
    // addr = (linear base + rowStep + kChunk*32) ^ ((row&7)<<4)
    int lrow = lane & 15;
    int lcol8 = lane >> 4;         // 0/1 -> k offset 0/8 halfs (16B)
    uint32_t aXm = (uint32_t)((m0w + lrow) & 7) << 4;   // row&7 invariant under +16 rows
    uint32_t bXm = (uint32_t)((n0w + lrow) & 7) << 4;
    uint32_t aLinBase = sb + (uint32_t)(m0w + lrow) * 128 + lcol8 * 16;
    uint32_t bLinBase = sb + A_ST + (uint32_t)(n0w + lrow) * 128 + lcol8 * 16;

    float acc[2][8][4];
#pragma unroll
    for (int mt = 0; mt < 2; mt++)
#pragma unroll
        for (int nt = 0; nt < 8; nt++)
#pragma unroll
            for (int j = 0; j < 4; j++) acc[mt][nt][j] = 0.f;

    // --- prologue: producer (tid 0) fills stages 0,1 ---
    if (tid == 0) {
#pragma unroll
        for (int s = 0; s < STAGES - 1; s++) {
            uint32_t so = sb + s * STAGE_BYTES;
            MBARRIER_EXPECT_TX(mbFull + 8 * s, STAGE_BYTES);
            TMA_LOAD_2D(so, &tmA, s * BK, m0, mbFull + 8 * s);
            TMA_LOAD_2D(so + A_ST, &tmB, s * BK, n0, mbFull + 8 * s);
        }
    }

    // pipeline state: sc = consume stage, pc = its full parity;
    // sf = fill stage for iter kt+2; pe = producer's empty parity.
    int sc = 0, pc = 0;
    int sf = 2, pe = 0;
    uint32_t rdy = 0;    // probe result for current stage (0 at kt=0 -> spin)

    for (int kt = 0; kt < KITERS; kt++) {
        if (!rdy) MBARRIER_WAIT_PARITY(mbFull + 8 * sc, pc);   // slow path only

        uint32_t so = sc * STAGE_BYTES;
        uint32_t aB = aLinBase + so, bB = bLinBase + so;

        // next-stage probe target (for step-8 issue below)
        int scn = (sc == STAGES - 1) ? 0 : sc + 1;
        int pcn = (sc == STAGES - 1) ? (pc ^ 1) : pc;

        // preload first fragments of this stage
        uint32_t af[2][2][4];        // [k16 buf][mt][frag]
        uint32_t bf[3][4];           // [step mod 3][frag] — distance-2 prefetch
        LDSM_X4(af[0][0][0], af[0][0][1], af[0][0][2], af[0][0][3], aB ^ aXm);
        LDSM_X4(af[0][1][0], af[0][1][1], af[0][1][2], af[0][1][3], (aB + 2048) ^ aXm);
        LDSM_X4(bf[0][0], bf[0][1], bf[0][2], bf[0][3], bB ^ bXm);                    // step 0
        LDSM_X4(bf[1][0], bf[1][1], bf[1][2], bf[1][3], (bB + 2048) ^ bXm);           // step 1

        // producer: fill stage sf for iter kt+2
        if (tid == 0 && kt + 2 < KITERS) {
            if (kt > 0) MBARRIER_WAIT_PARITY_RELAXED(mbEmpty + 8 * sf, pe);
            uint32_t soN = sb + sf * STAGE_BYTES;
            MBARRIER_EXPECT_TX(mbFull + 8 * sf, STAGE_BYTES);
            TMA_LOAD_2D(soN, &tmA, (kt + 2) * BK, m0, mbFull + 8 * sf);
            TMA_LOAD_2D(soN + A_ST, &tmB, (kt + 2) * BK, n0, mbFull + 8 * sf);
        }

        // 16 software-pipelined (k16, nq) steps; B prefetch distance 2
#pragma unroll
        for (int s = 0; s < 16; s++) {
            const int ks = s >> 2, nq = s & 3;
            const int cb = ks & 1, sbuf = s % 3;
            if (nq == 0 && ks < 3) {     // prefetch next k16's A frags
                const int kn = ks + 1, an = kn & 1;
                LDSM_X4(af[an][0][0], af[an][0][1], af[an][0][2], af[an][0][3],
                        (aB + kn * 32) ^ aXm);
                LDSM_X4(af[an][1][0], af[an][1][1], af[an][1][2], af[an][1][3],
                        (aB + 2048 + kn * 32) ^ aXm);
            }
            if (s < 14) {                // prefetch step s+2's B frags
                const int s2 = s + 2, ks2 = s2 >> 2, nq2 = s2 & 3, bn = s2 % 3;
                LDSM_X4(bf[bn][0], bf[bn][1], bf[bn][2], bf[bn][3],
                        (bB + nq2 * 2048 + ks2 * 32) ^ bXm);
            }
            if (s == 8) {                // non-blocking probe for next stage;
                if (kt + 1 < KITERS) {   // latency covered by steps 9..15
                    MBARRIER_TRY_PROBE(mbFull + 8 * scn, pcn, rdy);
                } else {
                    rdy = 1;
                }
            }
#pragma unroll
            for (int mt = 0; mt < 2; mt++) {
                MMA_16816(acc[mt][2 * nq], af[cb][mt][0], af[cb][mt][1],
                          af[cb][mt][2], af[cb][mt][3], bf[sbuf][0], bf[sbuf][2]);
                MMA_16816(acc[mt][2 * nq + 1], af[cb][mt][0], af[cb][mt][1],
                          af[cb][mt][2], af[cb][mt][3], bf[sbuf][1], bf[sbuf][3]);
            }
        }

        // warp-collective MMAs consumed all this warp's reads of stage sc;
        // single lane releases for the whole warp (empty count = 8)
        if (lane == 0) MBARRIER_ARRIVE(mbEmpty + 8 * sc);

        // advance stage counters / parities
        if (sc == 0 && kt > 0) pe ^= 1;
        sc = scn; pc = pcn;
        if (++sf == STAGES) { sf = 0; }
    }

    // --- epilogue ---
    int gq = lane >> 2, t4 = lane & 3;
#pragma unroll
    for (int mt = 0; mt < 2; mt++) {
        int mrow0 = m0 + m0w + mt * 16 + gq;
#pragma unroll
        for (int nt = 0; nt < 8; nt++) {
            int ncol = n0 + n0w + nt * 8 + t4 * 2;
            float2 v0 = make_float2(acc[mt][nt][0], acc[mt][nt][1]);
            float2 v1 = make_float2(acc[mt][nt][2], acc[mt][nt][3]);
            *reinterpret_cast<float2*>(&out[(size_t)mrow0 * N_DIM + ncol]) = v0;
            *reinterpret_cast<float2*>(&out[(size_t)(mrow0 + 8) * N_DIM + ncol]) = v1;
        }
    }
}

// ---------------- host launch ----------------------------------------------
typedef CUresult (*PFN_tmapEncode)(CUtensorMap*, CUtensorMapDataType, cuuint32_t, void*,
                                   const cuuint64_t*, const cuuint64_t*, const cuuint32_t*,
                                   const cuuint32_t*, CUtensorMapInterleave, CUtensorMapSwizzle,
                                   CUtensorMapL2promotion, CUtensorMapFloatOOBfill);

extern "C" void kernel_launch(void* const* d_in, const int* in_sizes, int n_in,
                              void* d_out, int out_size) {
    const float* A = (const float*)d_in[0];
    const int*   W = (const int*)d_in[1];
    const float* S = (const float*)d_in[2];
    const int*   Z = (const int*)d_in[3];
    float* out = (float*)d_out;

    void* pAh = nullptr;
    void* pWt = nullptr;
    cudaGetSymbolAddress(&pAh, g_Ah);
    cudaGetSymbolAddress(&pWt, g_Wt);

    PFN_tmapEncode enc = nullptr;
    cudaDriverEntryPointQueryResult qr;
    cudaGetDriverEntryPointByVersion("cuTensorMapEncodeTiled", (void**)&enc, 12000,
                                     cudaEnableDefault, &qr);

    CUtensorMap tmA, tmB;
    {
        cuuint64_t dims[2]    = {K_DIM, M_DIM};
        cuuint64_t strides[1] = {K_DIM * 2};
        cuuint32_t box[2]     = {BK, BM};       // 64 fp16 = 128B row (SW128), 128 rows
        cuuint32_t es[2]      = {1, 1};
        enc(&tmA, CU_TENSOR_MAP_DATA_TYPE_FLOAT16, 2, pAh, dims, strides, box, es,
            CU_TENSOR_MAP_INTERLEAVE_NONE, CU_TENSOR_MAP_SWIZZLE_128B,
            CU_TENSOR_MAP_L2_PROMOTION_L2_128B, CU_TENSOR_MAP_FLOAT_OOB_FILL_NONE);
    }
    {
        cuuint64_t dims[2]    = {K_DIM, N_DIM};
        cuuint64_t strides[1] = {K_DIM * 2};
        cuuint32_t box[2]     = {BK, BN};
        cuuint32_t es[2]      = {1, 1};
        enc(&tmB, CU_TENSOR_MAP_DATA_TYPE_FLOAT16, 2, pWt, dims, strides, box, es,
            CU_TENSOR_MAP_INTERLEAVE_NONE, CU_TENSOR_MAP_SWIZZLE_128B,
            CU_TENSOR_MAP_L2_PROMOTION_L2_128B, CU_TENSOR_MAP_FLOAT_OOB_FILL_NONE);
    }

    cudaFuncSetAttribute(gemm_kernel, cudaFuncAttributeMaxDynamicSharedMemorySize, GEMM_SMEM);

    prep_kernel<<<A_BLOCKS + W_BLOCKS, 256>>>(A, W, S, Z);
    gemm_kernel<<<TM_TILES * TN_TILES, 256, GEMM_SMEM>>>(tmA, tmB, out);
}